// round 2
// baseline (speedup 1.0000x reference)
#include <cuda_runtime.h>
#include <cuda_bf16.h>

#define QN 16384
#define SN 16384
#define FD 64
#define HN 32
#define EN 393216

// ---------------- static device scratch (no allocations allowed) ----------------
__device__ float g_xK [QN*FD];
__device__ float g_xV [QN*FD];
__device__ float g_xQ1[QN*FD];
__device__ float g_xMk[QN*FD];
__device__ float g_sQ2 [SN*FD];
__device__ float g_sidK[SN*FD];
__device__ float g_sidV[SN*FD];
__device__ float g_W1K[FD*FD], g_W1V[FD*FD], g_MK[FD*FD], g_MV[FD*FD], g_cV[FD];

__device__ int g_scnt[SN], g_qcnt[QN], g_scur[SN], g_qcur[QN];
__device__ int g_soff[SN+1], g_qoff[QN+1];
__device__ int g_eq_by_s[EN];   // qid of edge at sid-sorted position
__device__ int g_rq_by_s[EN];   // qid-sorted position of edge at sid-sorted position
__device__ int g_sid_by_q[EN];  // sid of edge at qid-sorted position

__device__ float g_agg[(size_t)EN*FD];  // hop-1 outputs, stored in qid-sorted order
__device__ float g_sc2[EN];             // hop-2 logits, qid-sorted order
__device__ float g_P[QN*FD], g_R[QN*FD], g_dsum[QN];
__device__ float g_chO[2][QN*FD];

// ---------------- tiny weight products ----------------
// W1K = Wf1@W_K2 ; W1V = Wf1@W_V2 ; MK = Wf2@W_K2 ; MV = Wf2@W_V2 ; cV = b_fuse@W_V2 + b_V2
__global__ void k_small(const float* __restrict__ W_fuse, const float* __restrict__ W_K2,
                        const float* __restrict__ W_V2, const float* __restrict__ b_fuse,
                        const float* __restrict__ b_V2) {
    int i = blockIdx.x, j = threadIdx.x;  // 64 x 64
    float s1k = 0.f, s1v = 0.f, smk = 0.f, smv = 0.f;
    for (int k = 0; k < FD; k++) {
        float wf1 = W_fuse[i*FD + k];
        float wf2 = W_fuse[(FD + i)*FD + k];
        float wk2 = W_K2[k*FD + j];
        float wv2 = W_V2[k*FD + j];
        s1k = fmaf(wf1, wk2, s1k);
        s1v = fmaf(wf1, wv2, s1v);
        smk = fmaf(wf2, wk2, smk);
        smv = fmaf(wf2, wv2, smv);
    }
    g_W1K[i*FD + j] = s1k; g_W1V[i*FD + j] = s1v;
    g_MK [i*FD + j] = smk; g_MV [i*FD + j] = smv;
    if (i == 0) {
        float c = 0.f;
        for (int k = 0; k < FD; k++) c = fmaf(b_fuse[k], W_V2[k*FD + j], c);
        g_cV[j] = c + b_V2[j];
    }
}

// ---------------- generic row GEMM: C[N,64] = A[N,64] @ B(64,64) (+bias) ----------------
__global__ void __launch_bounds__(128) k_gemm(const float* __restrict__ A,
                                              const float* __restrict__ B,
                                              const float* __restrict__ bias,
                                              float* __restrict__ C,
                                              int N, int transB, int addBias) {
    __shared__ float Bs[FD*FD];
    int t = threadIdx.x;
    for (int idx = t; idx < FD*FD; idx += blockDim.x) {
        int k = idx >> 6, j = idx & 63;
        Bs[idx] = transB ? B[j*FD + k] : B[idx];
    }
    __syncthreads();
    int r = blockIdx.x * blockDim.x + t;
    if (r >= N) return;
    float acc[FD];
#pragma unroll
    for (int j = 0; j < FD; j++) acc[j] = addBias ? bias[j] : 0.f;
    const float* a = A + (size_t)r * FD;
    for (int k = 0; k < FD; k++) {
        float av = a[k];
#pragma unroll
        for (int j = 0; j < FD; j++) acc[j] = fmaf(av, Bs[k*FD + j], acc[j]);
    }
    float* c = C + (size_t)r * FD;
#pragma unroll
    for (int j = 0; j < FD; j++) c[j] = acc[j];
}

// ---------------- counting sort ----------------
__global__ void k_zero_counts() {
    int i = blockIdx.x * blockDim.x + threadIdx.x;
    if (i < SN) { g_scnt[i] = 0; g_scur[i] = 0; }
    if (i < QN) { g_qcnt[i] = 0; g_qcur[i] = 0; }
}

__global__ void k_hist(const int* __restrict__ esid, const int* __restrict__ eqid) {
    int i = blockIdx.x * blockDim.x + threadIdx.x;
    if (i >= EN) return;
    atomicAdd(&g_scnt[esid[i]], 1);
    atomicAdd(&g_qcnt[eqid[i]], 1);
}

// exclusive scan of 16384 ints, single block of 1024 threads
// mode 0: scnt -> soff ; mode 1: qcnt -> qoff  (globals referenced in device code)
__global__ void __launch_bounds__(1024) k_scan16k(int mode) {
    const int* cnt = mode ? g_qcnt : g_scnt;
    int* off       = mode ? g_qoff : g_soff;
    __shared__ int sm[1024];
    int t = threadIdx.x;
    int base = t * 16;
    int loc[16];
    int s = 0;
#pragma unroll
    for (int k = 0; k < 16; k++) { loc[k] = s; s += cnt[base + k]; }
    sm[t] = s;
    __syncthreads();
    for (int o = 1; o < 1024; o <<= 1) {
        int v = (t >= o) ? sm[t - o] : 0;
        __syncthreads();
        sm[t] += v;
        __syncthreads();
    }
    int pre = (t > 0) ? sm[t - 1] : 0;
#pragma unroll
    for (int k = 0; k < 16; k++) off[base + k] = pre + loc[k];
    if (t == 1023) off[16384] = sm[1023];
}

__global__ void k_scatter(const int* __restrict__ esid, const int* __restrict__ eqid) {
    int i = blockIdx.x * blockDim.x + threadIdx.x;
    if (i >= EN) return;
    int s = esid[i], q = eqid[i];
    int ps = g_soff[s] + atomicAdd(&g_scur[s], 1);
    int pq = g_qoff[q] + atomicAdd(&g_qcur[q], 1);
    g_eq_by_s[ps] = q;
    g_rq_by_s[ps] = pq;
    g_sid_by_q[pq] = s;
}

// ---------------- pass A: hop-1 attention, one warp per student ----------------
// per-warp smem: sKT[64][33] (2112) + sV[32][65] (2080) = 4192 floats, stride 4224
#define WARP_SMEM 4224
__global__ void __launch_bounds__(128) k_passA(const float* __restrict__ x,
                                               const int* __restrict__ hist_qid,
                                               const int* __restrict__ hist_cnt) {
    extern __shared__ float smA[];
    int lane = threadIdx.x & 31;
    int wib  = threadIdx.x >> 5;
    int s = blockIdx.x * 4 + wib;
    float* sKT = smA + wib * WARP_SMEM;  // [feature j][hist h], pad 33 -> conflict-free
    float* sV  = sKT + 2112;             // [hist h][feature f], pad 65 -> conflict-free

    float sq2a = g_sQ2 [s*FD + lane],      sq2b = g_sQ2 [s*FD + 32 + lane];
    float skA  = g_sidK[s*FD + lane],      skB  = g_sidK[s*FD + 32 + lane];
    int cnt = hist_cnt[s];
    cnt = min(max(cnt, 0), HN);

    if (lane < cnt) {
        int hid = hist_qid[s*HN + lane];
        const float4* kr = (const float4*)(g_xK + (size_t)hid * FD);
        const float4* vr = (const float4*)(g_xV + (size_t)hid * FD);
#pragma unroll
        for (int j4 = 0; j4 < 16; j4++) {
            float4 kv = kr[j4];
            sKT[(4*j4 + 0)*33 + lane] = kv.x;
            sKT[(4*j4 + 1)*33 + lane] = kv.y;
            sKT[(4*j4 + 2)*33 + lane] = kv.z;
            sKT[(4*j4 + 3)*33 + lane] = kv.w;
            float4 vv = vr[j4];
            float* vrow = sV + lane*65 + 4*j4;
            vrow[0] = vv.x; vrow[1] = vv.y; vrow[2] = vv.z; vrow[3] = vv.w;
        }
    }
    __syncwarp();

    int beg = g_soff[s], end = g_soff[s + 1];
    const float kScale = 0.125f;  // 1/sqrt(64)

    for (int i = beg; i < end; i++) {
        int qid = g_eq_by_s[i];
        int rq  = g_rq_by_s[i];
        const float* xq1 = g_xQ1 + (size_t)qid * FD;
        float qa = xq1[lane]      + sq2a;   // q[lane]
        float qb = xq1[32 + lane] + sq2b;   // q[lane+32]

        // scores: lane h computes q . K_h
        float sc = 0.f;
#pragma unroll
        for (int j = 0; j < 32; j++) {
            float qv = __shfl_sync(0xffffffffu, qa, j);
            sc = fmaf(qv, sKT[j*33 + lane], sc);
        }
#pragma unroll
        for (int j = 0; j < 32; j++) {
            float qv = __shfl_sync(0xffffffffu, qb, j);
            sc = fmaf(qv, sKT[(32 + j)*33 + lane], sc);
        }
        sc *= kScale;

        // masked softmax over lanes < cnt
        float scm = (lane < cnt) ? sc : -3.4e38f;
#pragma unroll
        for (int o = 16; o > 0; o >>= 1) scm = fmaxf(scm, __shfl_xor_sync(0xffffffffu, scm, o));
        float ex = (lane < cnt) ? __expf(sc - scm) : 0.f;
        float den = ex;
#pragma unroll
        for (int o = 16; o > 0; o >>= 1) den += __shfl_xor_sync(0xffffffffu, den, o);
        float a = (den > 0.f) ? ex / den : 0.f;

        // agg_f = sum_h a_h * V[h][f]; lane owns features (lane, lane+32)
        float a0 = 0.f, a1 = 0.f;
        for (int h = 0; h < cnt; h++) {
            float ah = __shfl_sync(0xffffffffu, a, h);
            const float* vrow = sV + h*65;
            a0 = fmaf(ah, vrow[lane], a0);
            a1 = fmaf(ah, vrow[32 + lane], a1);
        }

        // hop-2 logit: scale * ( x[qid].sidK[s] + agg . xMk[qid] )
        const float* xr = x     + (size_t)qid * FD;
        const float* mk = g_xMk + (size_t)qid * FD;
        float p = xr[lane]*skA + xr[32 + lane]*skB
                + a0*mk[lane]  + a1*mk[32 + lane];
#pragma unroll
        for (int o = 16; o > 0; o >>= 1) p += __shfl_xor_sync(0xffffffffu, p, o);

        float* ag = g_agg + (size_t)rq * FD;
        ag[lane]      = a0;
        ag[32 + lane] = a1;
        if (lane == 0) g_sc2[rq] = kScale * p;
    }
}

// ---------------- pass B: segment online softmax, one warp per question ----------------
__global__ void __launch_bounds__(256) k_passB() {
    int lane = threadIdx.x & 31;
    int q = blockIdx.x * 8 + (threadIdx.x >> 5);
    int beg = g_qoff[q], end = g_qoff[q + 1];
    float m = -3.4e38f, d = 0.f, P0 = 0.f, P1 = 0.f, R0 = 0.f, R1 = 0.f;
    for (int i = beg; i < end; i++) {
        float sc = g_sc2[i];
        int sid = g_sid_by_q[i];
        float nm = fmaxf(m, sc);
        float r = __expf(m - nm);
        float e = __expf(sc - nm);
        m = nm;
        const float* sv = g_sidV + (size_t)sid * FD;
        const float* ag = g_agg  + (size_t)i * FD;
        d  = d * r + e;
        P0 = fmaf(e, sv[lane],      P0 * r);
        P1 = fmaf(e, sv[32 + lane], P1 * r);
        R0 = fmaf(e, ag[lane],      R0 * r);
        R1 = fmaf(e, ag[32 + lane], R1 * r);
    }
    g_P[q*FD + lane] = P0; g_P[q*FD + 32 + lane] = P1;
    g_R[q*FD + lane] = R0; g_R[q*FD + 32 + lane] = R1;
    if (lane == 0) g_dsum[q] = d;
}

// ---------------- finalize: out_ch[q] = (P + R@MV + d*cV)/max(d,1e-9) ----------------
__global__ void __launch_bounds__(256) k_finalize(int ch) {
    __shared__ float MVs[FD*FD];
    __shared__ float cVs[FD];
    __shared__ float rb[8][FD];
    int t = threadIdx.x;
    for (int i = t; i < FD*FD; i += 256) MVs[i] = g_MV[i];
    if (t < FD) cVs[t] = g_cV[t];
    __syncthreads();
    int lane = t & 31, w = t >> 5;
    int q = blockIdx.x * 8 + w;
    float R0 = g_R[q*FD + lane], R1 = g_R[q*FD + 32 + lane];
    float P0 = g_P[q*FD + lane], P1 = g_P[q*FD + 32 + lane];
    float d = g_dsum[q];
    rb[w][lane] = R0; rb[w][32 + lane] = R1;
    __syncwarp();
    float o0 = fmaf(d, cVs[lane],      P0);
    float o1 = fmaf(d, cVs[32 + lane], P1);
#pragma unroll
    for (int i2 = 0; i2 < FD; i2++) {
        float ri = rb[w][i2];
        o0 = fmaf(ri, MVs[i2*FD + lane],      o0);
        o1 = fmaf(ri, MVs[i2*FD + 32 + lane], o1);
    }
    float inv = 1.f / fmaxf(d, 1e-9f);
    float* o = &g_chO[ch][(size_t)q * FD];
    o[lane]      = o0 * inv;
    o[32 + lane] = o1 * inv;
}

// ---------------- final projection: out = [pos|neg] @ W_proj + b_proj ----------------
__global__ void __launch_bounds__(128) k_project(const float* __restrict__ Wp,
                                                 const float* __restrict__ bp,
                                                 float* __restrict__ out) {
    __shared__ float W1s[FD*FD], W2s[FD*FD];
    int t = threadIdx.x;
    for (int i = t; i < FD*FD; i += 128) { W1s[i] = Wp[i]; W2s[i] = Wp[FD*FD + i]; }
    __syncthreads();
    int q = blockIdx.x * 128 + t;
    float acc[FD];
#pragma unroll
    for (int j = 0; j < FD; j++) acc[j] = bp[j];
    const float* pr = &g_chO[0][(size_t)q * FD];
    const float* nr = &g_chO[1][(size_t)q * FD];
    for (int k = 0; k < FD; k++) {
        float pv = pr[k], nv = nr[k];
#pragma unroll
        for (int j = 0; j < FD; j++)
            acc[j] = fmaf(pv, W1s[k*FD + j], fmaf(nv, W2s[k*FD + j], acc[j]));
    }
    float* o = out + (size_t)q * FD;
#pragma unroll
    for (int j = 0; j < FD; j++) o[j] = acc[j];
}

// ---------------- launch ----------------
extern "C" void kernel_launch(void* const* d_in, const int* in_sizes, int n_in,
                              void* d_out, int out_size) {
    const float* x      = (const float*)d_in[0];
    const float* s_emb  = (const float*)d_in[1];
    const float* W_Q    = (const float*)d_in[2];
    const float* b_Q    = (const float*)d_in[3];
    const float* W_K    = (const float*)d_in[4];
    const float* b_K    = (const float*)d_in[5];
    const float* W_V    = (const float*)d_in[6];
    const float* b_V    = (const float*)d_in[7];
    const float* W_fuse = (const float*)d_in[8];
    const float* b_fuse = (const float*)d_in[9];
    const float* W_K2   = (const float*)d_in[10];
    // const float* b_K2 = (const float*)d_in[11];   // softmax-invariant, dropped
    const float* W_V2   = (const float*)d_in[12];
    const float* b_V2   = (const float*)d_in[13];
    const float* W_proj = (const float*)d_in[14];
    const float* b_proj = (const float*)d_in[15];
    // h1_bias (16), h2_bias (17): softmax-invariant, dropped
    const int* hist_qid_pos = (const int*)d_in[18];
    const int* hist_cnt_pos = (const int*)d_in[19];
    const int* hist_qid_neg = (const int*)d_in[20];
    const int* hist_cnt_neg = (const int*)d_in[21];
    const int* edge_sid_pos = (const int*)d_in[22];
    const int* edge_qid_pos = (const int*)d_in[23];
    const int* edge_sid_neg = (const int*)d_in[24];
    const int* edge_qid_neg = (const int*)d_in[25];
    float* out = (float*)d_out;

    // Resolve DEVICE addresses of __device__ globals (host-side symbol shadow
    // addresses are NOT valid device pointers — this was the R1 bug).
    float *p_xK, *p_xV, *p_xQ1, *p_xMk, *p_sQ2, *p_sidK, *p_sidV;
    float *p_W1K, *p_W1V, *p_MK;
    cudaGetSymbolAddress((void**)&p_xK,   g_xK);
    cudaGetSymbolAddress((void**)&p_xV,   g_xV);
    cudaGetSymbolAddress((void**)&p_xQ1,  g_xQ1);
    cudaGetSymbolAddress((void**)&p_xMk,  g_xMk);
    cudaGetSymbolAddress((void**)&p_sQ2,  g_sQ2);
    cudaGetSymbolAddress((void**)&p_sidK, g_sidK);
    cudaGetSymbolAddress((void**)&p_sidV, g_sidV);
    cudaGetSymbolAddress((void**)&p_W1K,  g_W1K);
    cudaGetSymbolAddress((void**)&p_W1V,  g_W1V);
    cudaGetSymbolAddress((void**)&p_MK,   g_MK);

    const int passA_smem = 4 * WARP_SMEM * sizeof(float);  // 67584 B
    cudaFuncSetAttribute(k_passA, cudaFuncAttributeMaxDynamicSharedMemorySize, passA_smem);

    // tiny weight products
    k_small<<<64, 64>>>(W_fuse, W_K2, W_V2, b_fuse, b_V2);

    // precompute projections
    k_gemm<<<QN/128, 128>>>(x,     W_K,         b_K, p_xK,   QN, 0, 1);
    k_gemm<<<QN/128, 128>>>(x,     W_V,         b_V, p_xV,   QN, 0, 1);
    k_gemm<<<QN/128, 128>>>(x,     W_Q,         b_Q, p_xQ1,  QN, 0, 0);
    k_gemm<<<QN/128, 128>>>(x,     p_MK,        b_Q, p_xMk,  QN, 1, 0);  // x @ MK^T
    k_gemm<<<SN/128, 128>>>(s_emb, W_Q + FD*FD, b_Q, p_sQ2,  SN, 0, 1);
    k_gemm<<<SN/128, 128>>>(s_emb, p_W1K,       b_Q, p_sidK, SN, 0, 0);
    k_gemm<<<SN/128, 128>>>(s_emb, p_W1V,       b_Q, p_sidV, SN, 0, 0);

    for (int ch = 0; ch < 2; ch++) {
        const int* esid = ch ? edge_sid_neg : edge_sid_pos;
        const int* eqid = ch ? edge_qid_neg : edge_qid_pos;
        const int* hq   = ch ? hist_qid_neg : hist_qid_pos;
        const int* hc   = ch ? hist_cnt_neg : hist_cnt_pos;

        k_zero_counts<<<SN/256, 256>>>();
        k_hist<<<EN/256, 256>>>(esid, eqid);
        k_scan16k<<<1, 1024>>>(0);
        k_scan16k<<<1, 1024>>>(1);
        k_scatter<<<EN/256, 256>>>(esid, eqid);

        k_passA<<<SN/4, 128, passA_smem>>>(x, hq, hc);
        k_passB<<<QN/8, 256>>>();
        k_finalize<<<QN/8, 256>>>(ch);
    }

    k_project<<<QN/128, 128>>>(W_proj, b_proj, out);
}

// round 3
// speedup vs baseline: 1.8346x; 1.8346x over previous
#include <cuda_runtime.h>
#include <cuda_bf16.h>

#define QN 16384
#define SN 16384
#define FD 64
#define HN 32
#define EN 393216

typedef unsigned long long ull;

// ---------------- packed f32x2 helpers (FFMA2 is PTX-only on sm_103a) ----------------
__device__ __forceinline__ ull pk2(float lo, float hi) {
    ull r; asm("mov.b64 %0,{%1,%2};" : "=l"(r) : "f"(lo), "f"(hi)); return r;
}
__device__ __forceinline__ void upk2(ull v, float& lo, float& hi) {
    asm("mov.b64 {%0,%1},%2;" : "=f"(lo), "=f"(hi) : "l"(v));
}
__device__ __forceinline__ ull fma2(ull a, ull b, ull c) {
    ull r; asm("fma.rn.f32x2 %0,%1,%2,%3;" : "=l"(r) : "l"(a), "l"(b), "l"(c)); return r;
}
__device__ __forceinline__ ull add2(ull a, ull b) {
    ull r; asm("add.rn.f32x2 %0,%1,%2;" : "=l"(r) : "l"(a), "l"(b)); return r;
}
__device__ __forceinline__ void lds2(ull& a, ull& b, unsigned addr) {
    asm volatile("ld.shared.v2.u64 {%0,%1},[%2];" : "=l"(a), "=l"(b) : "r"(addr));
}
__device__ __forceinline__ void ldg2(ull& a, ull& b, const void* p) {
    asm volatile("ld.global.nc.v2.u64 {%0,%1},[%2];" : "=l"(a), "=l"(b) : "l"(p));
}
__device__ __forceinline__ void stg2(void* p, ull a, ull b) {
    asm volatile("st.global.v2.u64 [%0],{%1,%2};" :: "l"(p), "l"(a), "l"(b) : "memory");
}
__device__ __forceinline__ unsigned su32(const void* p) {
    unsigned r;
    asm("{ .reg .u64 t; cvta.to.shared.u64 t, %1; cvt.u32.u64 %0, t; }" : "=r"(r) : "l"(p));
    return r;
}

// ---------------- static device scratch ----------------
__device__ __align__(128) float g_xK [QN*FD];
__device__ __align__(128) float g_xV [QN*FD];
__device__ __align__(128) float g_xQ1[QN*FD];
__device__ __align__(128) float g_xMk[QN*FD];
__device__ __align__(128) float g_sQ2 [SN*FD];
__device__ __align__(128) float g_sidK[SN*FD];
__device__ __align__(128) float g_sidV[SN*FD];
__device__ __align__(128) float g_W1K[FD*FD], g_W1V[FD*FD], g_MK[FD*FD], g_MV[FD*FD], g_cV[FD];

__device__ int g_scnt[SN], g_qcnt[QN], g_scur[SN], g_qcur[QN];
__device__ int g_soff[SN+1], g_qoff[QN+1];
__device__ int g_eq_by_s[EN];
__device__ int g_rq_by_s[EN];
__device__ int g_sid_by_q[EN];

__device__ __align__(128) float g_agg[(size_t)EN*FD];
__device__ float g_sc2[EN];
__device__ float g_P[QN*FD], g_R[QN*FD], g_dsum[QN];
__device__ float g_chO[2][QN*FD];

// ---------------- tiny weight products ----------------
__global__ void k_small(const float* __restrict__ W_fuse, const float* __restrict__ W_K2,
                        const float* __restrict__ W_V2, const float* __restrict__ b_fuse,
                        const float* __restrict__ b_V2) {
    int i = blockIdx.x, j = threadIdx.x;
    float s1k = 0.f, s1v = 0.f, smk = 0.f, smv = 0.f;
    for (int k = 0; k < FD; k++) {
        float wf1 = W_fuse[i*FD + k];
        float wf2 = W_fuse[(FD + i)*FD + k];
        float wk2 = W_K2[k*FD + j];
        float wv2 = W_V2[k*FD + j];
        s1k = fmaf(wf1, wk2, s1k);
        s1v = fmaf(wf1, wv2, s1v);
        smk = fmaf(wf2, wk2, smk);
        smv = fmaf(wf2, wv2, smv);
    }
    g_W1K[i*FD + j] = s1k; g_W1V[i*FD + j] = s1v;
    g_MK [i*FD + j] = smk; g_MV [i*FD + j] = smv;
    if (i == 0) {
        float c = 0.f;
        for (int k = 0; k < FD; k++) c = fmaf(b_fuse[k], W_V2[k*FD + j], c);
        g_cV[j] = c + b_V2[j];
    }
}

// ---------------- fused prep: 7 row-GEMMs in one launch ----------------
// grid = (QN/128, 4 colgroups, 7 jobs), block = 128
__global__ void __launch_bounds__(128) k_prep(const float* __restrict__ x,
                                              const float* __restrict__ s_emb,
                                              const float* __restrict__ W_Q,
                                              const float* __restrict__ b_Q,
                                              const float* __restrict__ W_K,
                                              const float* __restrict__ b_K,
                                              const float* __restrict__ W_V,
                                              const float* __restrict__ b_V) {
    int job = blockIdx.z, cq = blockIdx.y, t = threadIdx.x;
    const float* A; const float* B; const float* bias = b_Q; float* C;
    int transB = 0, addBias = 0;
    switch (job) {
        case 0: A = x;     B = W_K;          bias = b_K; C = g_xK;   addBias = 1; break;
        case 1: A = x;     B = W_V;          bias = b_V; C = g_xV;   addBias = 1; break;
        case 2: A = x;     B = W_Q;                      C = g_xQ1;               break;
        case 3: A = x;     B = g_MK;                     C = g_xMk;  transB = 1;  break;
        case 4: A = s_emb; B = W_Q + FD*FD;  bias = b_Q; C = g_sQ2;  addBias = 1; break;
        case 5: A = s_emb; B = g_W1K;                    C = g_sidK;              break;
        default:A = s_emb; B = g_W1V;                    C = g_sidV;              break;
    }
    __shared__ float Bs[FD*16];
    for (int idx = t; idx < FD*16; idx += 128) {
        int k = idx >> 4, j = idx & 15;
        Bs[idx] = transB ? B[(cq*16 + j)*FD + k] : B[k*FD + cq*16 + j];
    }
    __syncthreads();
    int r = blockIdx.x * 128 + t;
    float acc[16];
#pragma unroll
    for (int j = 0; j < 16; j++) acc[j] = addBias ? bias[cq*16 + j] : 0.f;
    const float4* a4 = (const float4*)(A + (size_t)r * FD);
#pragma unroll
    for (int k4 = 0; k4 < 16; k4++) {
        float4 av = a4[k4];
        const float* bp = Bs + k4*4*16;
#pragma unroll
        for (int j = 0; j < 16; j++) acc[j] = fmaf(av.x, bp[j],      acc[j]);
#pragma unroll
        for (int j = 0; j < 16; j++) acc[j] = fmaf(av.y, bp[16 + j], acc[j]);
#pragma unroll
        for (int j = 0; j < 16; j++) acc[j] = fmaf(av.z, bp[32 + j], acc[j]);
#pragma unroll
        for (int j = 0; j < 16; j++) acc[j] = fmaf(av.w, bp[48 + j], acc[j]);
    }
    float4* c4 = (float4*)(C + (size_t)r * FD + cq*16);
#pragma unroll
    for (int j4 = 0; j4 < 4; j4++)
        c4[j4] = make_float4(acc[4*j4], acc[4*j4+1], acc[4*j4+2], acc[4*j4+3]);
}

// ---------------- counting sort ----------------
__global__ void k_zero_counts() {
    int i = blockIdx.x * blockDim.x + threadIdx.x;
    if (i < SN) { g_scnt[i] = 0; g_scur[i] = 0; }
    if (i < QN) { g_qcnt[i] = 0; g_qcur[i] = 0; }
}

__global__ void k_hist(const int* __restrict__ esid, const int* __restrict__ eqid) {
    int i = blockIdx.x * blockDim.x + threadIdx.x;
    if (i >= EN) return;
    atomicAdd(&g_scnt[esid[i]], 1);
    atomicAdd(&g_qcnt[eqid[i]], 1);
}

__global__ void __launch_bounds__(1024) k_scan16k(int mode) {
    const int* cnt = mode ? g_qcnt : g_scnt;
    int* off       = mode ? g_qoff : g_soff;
    __shared__ int sm[1024];
    int t = threadIdx.x;
    int base = t * 16;
    int loc[16];
    int s = 0;
#pragma unroll
    for (int k = 0; k < 16; k++) { loc[k] = s; s += cnt[base + k]; }
    sm[t] = s;
    __syncthreads();
    for (int o = 1; o < 1024; o <<= 1) {
        int v = (t >= o) ? sm[t - o] : 0;
        __syncthreads();
        sm[t] += v;
        __syncthreads();
    }
    int pre = (t > 0) ? sm[t - 1] : 0;
#pragma unroll
    for (int k = 0; k < 16; k++) off[base + k] = pre + loc[k];
    if (t == 1023) off[16384] = sm[1023];
}

__global__ void k_scatter(const int* __restrict__ esid, const int* __restrict__ eqid) {
    int i = blockIdx.x * blockDim.x + threadIdx.x;
    if (i >= EN) return;
    int s = esid[i], q = eqid[i];
    int ps = g_soff[s] + atomicAdd(&g_scur[s], 1);
    int pq = g_qoff[q] + atomicAdd(&g_qcur[q], 1);
    g_eq_by_s[ps] = q;
    g_rq_by_s[ps] = pq;
    g_sid_by_q[pq] = s;
}

// ---------------- pass A: lane-owns-edge hop-1 attention ----------------
// warp = one student; lanes = 32 edges per sweep; K/V smem reads are broadcasts.
#define PAD_ROW 68              // floats per K/V row (4-phase STS, broadcast reads)
#define PA_WSM  (2*32*PAD_ROW + 128)   // per-warp smem floats = 4480
__global__ void __launch_bounds__(128, 3) k_passA(const float* __restrict__ x,
                                                  const int* __restrict__ hist_qid,
                                                  const int* __restrict__ hist_cnt) {
    extern __shared__ float smA[];
    int lane = threadIdx.x & 31;
    int w    = threadIdx.x >> 5;
    int s    = blockIdx.x * 4 + w;
    float* sK  = smA + w * PA_WSM;
    float* sV  = sK + 32*PAD_ROW;
    float* sQ  = sV + 32*PAD_ROW;     // 64 floats: sQ2 row
    float* sSK = sQ + 64;             // 64 floats: sidK row

    int cnt = hist_cnt[s];
    cnt = min(max(cnt, 0), HN);

    // load this lane's history row (zeros beyond cnt so garbage never enters math)
    if (lane < cnt) {
        int hid = hist_qid[s*HN + lane];
        const float4* kr = (const float4*)(g_xK + (size_t)hid * FD);
        const float4* vr = (const float4*)(g_xV + (size_t)hid * FD);
#pragma unroll
        for (int j = 0; j < 16; j++) {
            *(float4*)(sK + lane*PAD_ROW + 4*j) = kr[j];
            *(float4*)(sV + lane*PAD_ROW + 4*j) = vr[j];
        }
    } else {
        float4 z = make_float4(0.f, 0.f, 0.f, 0.f);
#pragma unroll
        for (int j = 0; j < 16; j++) {
            *(float4*)(sK + lane*PAD_ROW + 4*j) = z;
            *(float4*)(sV + lane*PAD_ROW + 4*j) = z;
        }
    }
    sQ [lane]      = g_sQ2 [s*FD + lane];
    sQ [lane + 32] = g_sQ2 [s*FD + lane + 32];
    sSK[lane]      = g_sidK[s*FD + lane];
    sSK[lane + 32] = g_sidK[s*FD + lane + 32];
    __syncwarp();

    unsigned sQb  = su32(sQ);
    unsigned sKb  = su32(sK);
    unsigned sVb  = su32(sV);
    unsigned sSKb = su32(sSK);

    int beg = g_soff[s], end = g_soff[s + 1];

    for (int b0 = beg; b0 < end; b0 += 32) {
        int i = b0 + lane;
        bool act = i < end;
        int ii = act ? i : (end - 1);
        int qid = g_eq_by_s[ii];
        int rq  = g_rq_by_s[ii];

        // q = xQ1[qid] + sQ2[s], packed f32x2
        ull q2[32];
        const char* xqp = (const char*)(g_xQ1 + (size_t)qid * FD);
#pragma unroll
        for (int j = 0; j < 16; j++) {
            ull a, b, c, d;
            ldg2(a, b, xqp + 16*j);
            lds2(c, d, sQb + 16*j);
            q2[2*j]   = add2(a, c);
            q2[2*j+1] = add2(b, d);
        }

        // scores (unscaled); h >= cnt -> -1e30
        float sc[32];
#pragma unroll
        for (int h = 0; h < 32; h++) {
            if (h < cnt) {
                unsigned kb = sKb + h * (PAD_ROW*4);
                ull acc0 = 0ull, acc1 = 0ull;
#pragma unroll
                for (int j = 0; j < 16; j++) {
                    ull ka, kb2;
                    lds2(ka, kb2, kb + 16*j);
                    acc0 = fma2(q2[2*j],   ka,  acc0);
                    acc1 = fma2(q2[2*j+1], kb2, acc1);
                }
                acc0 = add2(acc0, acc1);
                float lo, hi; upk2(acc0, lo, hi);
                sc[h] = lo + hi;
            } else {
                sc[h] = -1e30f;
            }
        }

        // in-lane masked softmax (scale folded into exp)
        float m = -1e30f;
#pragma unroll
        for (int h = 0; h < 32; h++) m = fmaxf(m, sc[h]);
        float den = 0.f;
#pragma unroll
        for (int h = 0; h < 32; h++) {
            float e = __expf((sc[h] - m) * 0.125f);
            sc[h] = e;
            den += e;
        }
        float inv = 1.f / den;   // den >= 1 always (max term = 1)

        // agg = sum_h a_h * V[h][:]
        ull agg2[32];
#pragma unroll
        for (int j = 0; j < 32; j++) agg2[j] = 0ull;
#pragma unroll
        for (int h = 0; h < 32; h++) {
            if (h < cnt) {
                float av = sc[h] * inv;
                ull aa = pk2(av, av);
                unsigned vb = sVb + h * (PAD_ROW*4);
#pragma unroll
                for (int j = 0; j < 16; j++) {
                    ull va, vb2;
                    lds2(va, vb2, vb + 16*j);
                    agg2[2*j]   = fma2(aa, va,  agg2[2*j]);
                    agg2[2*j+1] = fma2(aa, vb2, agg2[2*j+1]);
                }
            }
        }

        // hop-2 logit: p = x[qid].sidK[s] + agg.xMk[qid]
        ull p0 = 0ull, p1 = 0ull;
        const char* xp = (const char*)(x     + (size_t)qid * FD);
        const char* mp = (const char*)(g_xMk + (size_t)qid * FD);
#pragma unroll
        for (int j = 0; j < 16; j++) {
            ull xa, xb, ka, kb2, ma, mb;
            ldg2(xa, xb, xp + 16*j);
            lds2(ka, kb2, sSKb + 16*j);
            p0 = fma2(xa, ka,  p0);
            p1 = fma2(xb, kb2, p1);
            ldg2(ma, mb, mp + 16*j);
            p0 = fma2(agg2[2*j],   ma, p0);
            p1 = fma2(agg2[2*j+1], mb, p1);
        }
        p0 = add2(p0, p1);
        float pl, ph; upk2(p0, pl, ph);
        float p = pl + ph;

        if (act) {
            char* op = (char*)(g_agg + (size_t)rq * FD);
#pragma unroll
            for (int j = 0; j < 16; j++) stg2(op + 16*j, agg2[2*j], agg2[2*j+1]);
            g_sc2[rq] = 0.125f * p;
        }
    }
}

// ---------------- pass B: segment online softmax, one warp per question ----------------
__global__ void __launch_bounds__(256) k_passB() {
    int lane = threadIdx.x & 31;
    int q = blockIdx.x * 8 + (threadIdx.x >> 5);
    int beg = g_qoff[q], end = g_qoff[q + 1];
    float m = -3.4e38f, d = 0.f, P0 = 0.f, P1 = 0.f, R0 = 0.f, R1 = 0.f;
    for (int i = beg; i < end; i++) {
        float sc = g_sc2[i];
        int sid = g_sid_by_q[i];
        float nm = fmaxf(m, sc);
        float r = __expf(m - nm);
        float e = __expf(sc - nm);
        m = nm;
        const float* sv = g_sidV + (size_t)sid * FD;
        const float* ag = g_agg  + (size_t)i * FD;
        d  = d * r + e;
        P0 = fmaf(e, sv[lane],      P0 * r);
        P1 = fmaf(e, sv[32 + lane], P1 * r);
        R0 = fmaf(e, ag[lane],      R0 * r);
        R1 = fmaf(e, ag[32 + lane], R1 * r);
    }
    g_P[q*FD + lane] = P0; g_P[q*FD + 32 + lane] = P1;
    g_R[q*FD + lane] = R0; g_R[q*FD + 32 + lane] = R1;
    if (lane == 0) g_dsum[q] = d;
}

// ---------------- finalize: out_ch[q] = (P + R@MV + d*cV)/max(d,1e-9) ----------------
__global__ void __launch_bounds__(256) k_finalize(int ch) {
    __shared__ float MVs[FD*FD];
    __shared__ float cVs[FD];
    __shared__ float rb[8][FD];
    int t = threadIdx.x;
    for (int i = t; i < FD*FD; i += 256) MVs[i] = g_MV[i];
    if (t < FD) cVs[t] = g_cV[t];
    __syncthreads();
    int lane = t & 31, w = t >> 5;
    int q = blockIdx.x * 8 + w;
    float R0 = g_R[q*FD + lane], R1 = g_R[q*FD + 32 + lane];
    float P0 = g_P[q*FD + lane], P1 = g_P[q*FD + 32 + lane];
    float d = g_dsum[q];
    rb[w][lane] = R0; rb[w][32 + lane] = R1;
    __syncwarp();
    float o0 = fmaf(d, cVs[lane],      P0);
    float o1 = fmaf(d, cVs[32 + lane], P1);
#pragma unroll
    for (int i2 = 0; i2 < FD; i2++) {
        float ri = rb[w][i2];
        o0 = fmaf(ri, MVs[i2*FD + lane],      o0);
        o1 = fmaf(ri, MVs[i2*FD + 32 + lane], o1);
    }
    float inv = 1.f / fmaxf(d, 1e-9f);
    float* o = &g_chO[ch][(size_t)q * FD];
    o[lane]      = o0 * inv;
    o[32 + lane] = o1 * inv;
}

// ---------------- final projection ----------------
__global__ void __launch_bounds__(128) k_project(const float* __restrict__ Wp,
                                                 const float* __restrict__ bp,
                                                 float* __restrict__ out) {
    __shared__ float W1s[FD*FD], W2s[FD*FD];
    int t = threadIdx.x;
    for (int i = t; i < FD*FD; i += 128) { W1s[i] = Wp[i]; W2s[i] = Wp[FD*FD + i]; }
    __syncthreads();
    int q = blockIdx.x * 128 + t;
    float acc[FD];
#pragma unroll
    for (int j = 0; j < FD; j++) acc[j] = bp[j];
    const float* pr = &g_chO[0][(size_t)q * FD];
    const float* nr = &g_chO[1][(size_t)q * FD];
    for (int k = 0; k < FD; k++) {
        float pv = pr[k], nv = nr[k];
#pragma unroll
        for (int j = 0; j < FD; j++)
            acc[j] = fmaf(pv, W1s[k*FD + j], fmaf(nv, W2s[k*FD + j], acc[j]));
    }
    float* o = out + (size_t)q * FD;
#pragma unroll
    for (int j = 0; j < FD; j++) o[j] = acc[j];
}

// ---------------- launch ----------------
extern "C" void kernel_launch(void* const* d_in, const int* in_sizes, int n_in,
                              void* d_out, int out_size) {
    const float* x      = (const float*)d_in[0];
    const float* s_emb  = (const float*)d_in[1];
    const float* W_Q    = (const float*)d_in[2];
    const float* b_Q    = (const float*)d_in[3];
    const float* W_K    = (const float*)d_in[4];
    const float* b_K    = (const float*)d_in[5];
    const float* W_V    = (const float*)d_in[6];
    const float* b_V    = (const float*)d_in[7];
    const float* W_fuse = (const float*)d_in[8];
    const float* b_fuse = (const float*)d_in[9];
    const float* W_K2   = (const float*)d_in[10];
    const float* W_V2   = (const float*)d_in[12];
    const float* b_V2   = (const float*)d_in[13];
    const float* W_proj = (const float*)d_in[14];
    const float* b_proj = (const float*)d_in[15];
    const int* hist_qid_pos = (const int*)d_in[18];
    const int* hist_cnt_pos = (const int*)d_in[19];
    const int* hist_qid_neg = (const int*)d_in[20];
    const int* hist_cnt_neg = (const int*)d_in[21];
    const int* edge_sid_pos = (const int*)d_in[22];
    const int* edge_qid_pos = (const int*)d_in[23];
    const int* edge_sid_neg = (const int*)d_in[24];
    const int* edge_qid_neg = (const int*)d_in[25];
    float* out = (float*)d_out;

    const int passA_smem = 4 * PA_WSM * sizeof(float);  // 71680 B
    cudaFuncSetAttribute(k_passA, cudaFuncAttributeMaxDynamicSharedMemorySize, passA_smem);

    k_small<<<64, 64>>>(W_fuse, W_K2, W_V2, b_fuse, b_V2);

    dim3 prepGrid(QN/128, 4, 7);
    k_prep<<<prepGrid, 128>>>(x, s_emb, W_Q, b_Q, W_K, b_K, W_V, b_V);

    for (int ch = 0; ch < 2; ch++) {
        const int* esid = ch ? edge_sid_neg : edge_sid_pos;
        const int* eqid = ch ? edge_qid_neg : edge_qid_pos;
        const int* hq   = ch ? hist_qid_neg : hist_qid_pos;
        const int* hc   = ch ? hist_cnt_neg : hist_cnt_pos;

        k_zero_counts<<<SN/256, 256>>>();
        k_hist<<<EN/256, 256>>>(esid, eqid);
        k_scan16k<<<1, 1024>>>(0);
        k_scan16k<<<1, 1024>>>(1);
        k_scatter<<<EN/256, 256>>>(esid, eqid);

        k_passA<<<SN/4, 128, passA_smem>>>(x, hq, hc);
        k_passB<<<QN/8, 256>>>();
        k_finalize<<<QN/8, 256>>>(ch);
    }

    k_project<<<QN/128, 128>>>(W_proj, b_proj, out);
}

// round 4
// speedup vs baseline: 2.1618x; 1.1784x over previous
#include <cuda_runtime.h>
#include <cuda_bf16.h>

#define QN 16384
#define SN 16384
#define FD 64
#define HN 32
#define EN 393216

typedef unsigned long long ull;

// ---------------- packed f32x2 + wide-load helpers ----------------
__device__ __forceinline__ ull pk2(float lo, float hi) {
    ull r; asm("mov.b64 %0,{%1,%2};" : "=l"(r) : "f"(lo), "f"(hi)); return r;
}
__device__ __forceinline__ void upk2(ull v, float& lo, float& hi) {
    asm("mov.b64 {%0,%1},%2;" : "=f"(lo), "=f"(hi) : "l"(v));
}
__device__ __forceinline__ ull fma2(ull a, ull b, ull c) {
    ull r; asm("fma.rn.f32x2 %0,%1,%2,%3;" : "=l"(r) : "l"(a), "l"(b), "l"(c)); return r;
}
__device__ __forceinline__ ull add2(ull a, ull b) {
    ull r; asm("add.rn.f32x2 %0,%1,%2;" : "=l"(r) : "l"(a), "l"(b)); return r;
}
__device__ __forceinline__ void lds2(ull& a, ull& b, unsigned addr) {
    asm volatile("ld.shared.v2.u64 {%0,%1},[%2];" : "=l"(a), "=l"(b) : "r"(addr));
}
// 256-bit global load/store (sm_100+)
__device__ __forceinline__ void ldg4(ull& a, ull& b, ull& c, ull& d, const void* p) {
    asm volatile("ld.global.nc.v4.u64 {%0,%1,%2,%3},[%4];"
                 : "=l"(a), "=l"(b), "=l"(c), "=l"(d) : "l"(p));
}
__device__ __forceinline__ void stg4(void* p, ull a, ull b, ull c, ull d) {
    asm volatile("st.global.v4.u64 [%0],{%1,%2,%3,%4};"
                 :: "l"(p), "l"(a), "l"(b), "l"(c), "l"(d) : "memory");
}
__device__ __forceinline__ unsigned su32(const void* p) {
    unsigned r;
    asm("{ .reg .u64 t; cvta.to.shared.u64 t, %1; cvt.u32.u64 %0, t; }" : "=r"(r) : "l"(p));
    return r;
}

// ---------------- static device scratch (per-channel where needed) ----------------
__device__ __align__(128) float g_xK [QN*FD];
__device__ __align__(128) float g_xV [QN*FD];
__device__ __align__(128) float g_xQ1[QN*FD];
__device__ __align__(128) float g_xMk[QN*FD];
__device__ __align__(128) float g_sQ2 [SN*FD];
__device__ __align__(128) float g_sidK[SN*FD];
__device__ __align__(128) float g_sidV[SN*FD];
__device__ __align__(128) float g_W1K[FD*FD], g_W1V[FD*FD], g_MK[FD*FD], g_MV[FD*FD], g_cV[FD];

__device__ int g_scnt[2][SN], g_qcnt[2][QN], g_scur[2][SN], g_qcur[2][QN];
__device__ int g_soff[2][SN+1], g_qoff[2][QN+1];
__device__ int g_eq_by_s[2][EN];
__device__ int g_rq_by_s[2][EN];
__device__ int g_sid_by_q[2][EN];

__device__ __align__(128) float g_agg[2][(size_t)EN*FD];   // ~201 MB
__device__ float g_sc2[2][EN];
__device__ float g_chO[2][QN*FD];

// ---------------- tiny weight products ----------------
__global__ void k_small(const float* __restrict__ W_fuse, const float* __restrict__ W_K2,
                        const float* __restrict__ W_V2, const float* __restrict__ b_fuse,
                        const float* __restrict__ b_V2) {
    int i = blockIdx.x, j = threadIdx.x;
    float s1k = 0.f, s1v = 0.f, smk = 0.f, smv = 0.f;
    for (int k = 0; k < FD; k++) {
        float wf1 = W_fuse[i*FD + k];
        float wf2 = W_fuse[(FD + i)*FD + k];
        float wk2 = W_K2[k*FD + j];
        float wv2 = W_V2[k*FD + j];
        s1k = fmaf(wf1, wk2, s1k);
        s1v = fmaf(wf1, wv2, s1v);
        smk = fmaf(wf2, wk2, smk);
        smv = fmaf(wf2, wv2, smv);
    }
    g_W1K[i*FD + j] = s1k; g_W1V[i*FD + j] = s1v;
    g_MK [i*FD + j] = smk; g_MV [i*FD + j] = smv;
    if (i == 0) {
        float c = 0.f;
        for (int k = 0; k < FD; k++) c = fmaf(b_fuse[k], W_V2[k*FD + j], c);
        g_cV[j] = c + b_V2[j];
    }
}

// ---------------- fused prep: 7 row-GEMMs in one launch ----------------
__global__ void __launch_bounds__(128) k_prep(const float* __restrict__ x,
                                              const float* __restrict__ s_emb,
                                              const float* __restrict__ W_Q,
                                              const float* __restrict__ b_Q,
                                              const float* __restrict__ W_K,
                                              const float* __restrict__ b_K,
                                              const float* __restrict__ W_V,
                                              const float* __restrict__ b_V) {
    int job = blockIdx.z, cq = blockIdx.y, t = threadIdx.x;
    const float* A; const float* B; const float* bias = b_Q; float* C;
    int transB = 0, addBias = 0;
    switch (job) {
        case 0: A = x;     B = W_K;          bias = b_K; C = g_xK;   addBias = 1; break;
        case 1: A = x;     B = W_V;          bias = b_V; C = g_xV;   addBias = 1; break;
        case 2: A = x;     B = W_Q;                      C = g_xQ1;               break;
        case 3: A = x;     B = g_MK;                     C = g_xMk;  transB = 1;  break;
        case 4: A = s_emb; B = W_Q + FD*FD;  bias = b_Q; C = g_sQ2;  addBias = 1; break;
        case 5: A = s_emb; B = g_W1K;                    C = g_sidK;              break;
        default:A = s_emb; B = g_W1V;                    C = g_sidV;              break;
    }
    __shared__ float Bs[FD*16];
    for (int idx = t; idx < FD*16; idx += 128) {
        int k = idx >> 4, j = idx & 15;
        Bs[idx] = transB ? B[(cq*16 + j)*FD + k] : B[k*FD + cq*16 + j];
    }
    __syncthreads();
    int r = blockIdx.x * 128 + t;
    float acc[16];
#pragma unroll
    for (int j = 0; j < 16; j++) acc[j] = addBias ? bias[cq*16 + j] : 0.f;
    const float4* a4 = (const float4*)(A + (size_t)r * FD);
#pragma unroll
    for (int k4 = 0; k4 < 16; k4++) {
        float4 av = a4[k4];
        const float* bp = Bs + k4*4*16;
#pragma unroll
        for (int j = 0; j < 16; j++) acc[j] = fmaf(av.x, bp[j],      acc[j]);
#pragma unroll
        for (int j = 0; j < 16; j++) acc[j] = fmaf(av.y, bp[16 + j], acc[j]);
#pragma unroll
        for (int j = 0; j < 16; j++) acc[j] = fmaf(av.z, bp[32 + j], acc[j]);
#pragma unroll
        for (int j = 0; j < 16; j++) acc[j] = fmaf(av.w, bp[48 + j], acc[j]);
    }
    float4* c4 = (float4*)(C + (size_t)r * FD + cq*16);
#pragma unroll
    for (int j4 = 0; j4 < 4; j4++)
        c4[j4] = make_float4(acc[4*j4], acc[4*j4+1], acc[4*j4+2], acc[4*j4+3]);
}

// ---------------- counting sort (both channels in each launch) ----------------
__global__ void k_zero_counts() {
    int i = blockIdx.x * blockDim.x + threadIdx.x;
    if (i < SN) {
        g_scnt[0][i] = 0; g_scur[0][i] = 0; g_scnt[1][i] = 0; g_scur[1][i] = 0;
        g_qcnt[0][i] = 0; g_qcur[0][i] = 0; g_qcnt[1][i] = 0; g_qcur[1][i] = 0;
    }
}

__global__ void k_hist(const int* __restrict__ sp, const int* __restrict__ qp,
                       const int* __restrict__ sn, const int* __restrict__ qn) {
    int i = (blockIdx.x * blockDim.x + threadIdx.x) * 4;
    if (i >= EN) return;
    int4 a = *(const int4*)(sp + i);
    int4 b = *(const int4*)(qp + i);
    int4 c = *(const int4*)(sn + i);
    int4 d = *(const int4*)(qn + i);
    atomicAdd(&g_scnt[0][a.x], 1); atomicAdd(&g_scnt[0][a.y], 1);
    atomicAdd(&g_scnt[0][a.z], 1); atomicAdd(&g_scnt[0][a.w], 1);
    atomicAdd(&g_qcnt[0][b.x], 1); atomicAdd(&g_qcnt[0][b.y], 1);
    atomicAdd(&g_qcnt[0][b.z], 1); atomicAdd(&g_qcnt[0][b.w], 1);
    atomicAdd(&g_scnt[1][c.x], 1); atomicAdd(&g_scnt[1][c.y], 1);
    atomicAdd(&g_scnt[1][c.z], 1); atomicAdd(&g_scnt[1][c.w], 1);
    atomicAdd(&g_qcnt[1][d.x], 1); atomicAdd(&g_qcnt[1][d.y], 1);
    atomicAdd(&g_qcnt[1][d.z], 1); atomicAdd(&g_qcnt[1][d.w], 1);
}

// 4 scans (s/q x ch), one block each, all in one launch
__global__ void __launch_bounds__(1024) k_scan16k() {
    int ch = blockIdx.x >> 1, mode = blockIdx.x & 1;
    const int* cnt = mode ? g_qcnt[ch] : g_scnt[ch];
    int* off       = mode ? g_qoff[ch] : g_soff[ch];
    __shared__ int sm[1024];
    int t = threadIdx.x;
    int base = t * 16;
    int loc[16];
    int s = 0;
#pragma unroll
    for (int k = 0; k < 16; k++) { loc[k] = s; s += cnt[base + k]; }
    sm[t] = s;
    __syncthreads();
    for (int o = 1; o < 1024; o <<= 1) {
        int v = (t >= o) ? sm[t - o] : 0;
        __syncthreads();
        sm[t] += v;
        __syncthreads();
    }
    int pre = (t > 0) ? sm[t - 1] : 0;
#pragma unroll
    for (int k = 0; k < 16; k++) off[base + k] = pre + loc[k];
    if (t == 1023) off[16384] = sm[1023];
}

__global__ void k_scatter(const int* __restrict__ sp, const int* __restrict__ qp,
                          const int* __restrict__ sn, const int* __restrict__ qn) {
    int ch = blockIdx.z;
    int i = blockIdx.x * blockDim.x + threadIdx.x;
    if (i >= EN) return;
    const int* es = ch ? sn : sp;
    const int* eq = ch ? qn : qp;
    int s = es[i], q = eq[i];
    int ps = g_soff[ch][s] + atomicAdd(&g_scur[ch][s], 1);
    int pq = g_qoff[ch][q] + atomicAdd(&g_qcur[ch][q], 1);
    g_eq_by_s[ch][ps] = q;
    g_rq_by_s[ch][ps] = pq;
    g_sid_by_q[ch][pq] = s;
}

// ---------------- pass A: lane-owns-edge hop-1 attention ----------------
#define PAD_ROW 68
#define PA_WSM  (2*32*PAD_ROW + 128)   // per-warp smem floats = 4480
__global__ void __launch_bounds__(128, 3) k_passA(const float* __restrict__ x,
                                                  const int* __restrict__ hqp,
                                                  const int* __restrict__ hcp,
                                                  const int* __restrict__ hqn,
                                                  const int* __restrict__ hcn) {
    extern __shared__ float smA[];
    int ch = blockIdx.z;
    const int* hist_qid = ch ? hqn : hqp;
    const int* hist_cnt = ch ? hcn : hcp;
    const int* eqs  = g_eq_by_s[ch];
    const int* rqs  = g_rq_by_s[ch];
    float* aggc = g_agg[ch];
    float* sc2c = g_sc2[ch];

    int lane = threadIdx.x & 31;
    int w    = threadIdx.x >> 5;
    int s    = blockIdx.x * 4 + w;
    float* sK  = smA + w * PA_WSM;
    float* sV  = sK + 32*PAD_ROW;
    float* sQ  = sV + 32*PAD_ROW;     // 64 floats: sQ2 row
    float* sSK = sQ + 64;             // 64 floats: sidK row

    int cnt = hist_cnt[s];
    cnt = min(max(cnt, 0), HN);

    if (lane < cnt) {
        int hid = hist_qid[s*HN + lane];
        const float4* kr = (const float4*)(g_xK + (size_t)hid * FD);
        const float4* vr = (const float4*)(g_xV + (size_t)hid * FD);
#pragma unroll
        for (int j = 0; j < 16; j++) {
            *(float4*)(sK + lane*PAD_ROW + 4*j) = kr[j];
            *(float4*)(sV + lane*PAD_ROW + 4*j) = vr[j];
        }
    } else {
        float4 z = make_float4(0.f, 0.f, 0.f, 0.f);
#pragma unroll
        for (int j = 0; j < 16; j++) {
            *(float4*)(sK + lane*PAD_ROW + 4*j) = z;
            *(float4*)(sV + lane*PAD_ROW + 4*j) = z;
        }
    }
    sQ [lane]      = g_sQ2 [s*FD + lane];
    sQ [lane + 32] = g_sQ2 [s*FD + lane + 32];
    sSK[lane]      = g_sidK[s*FD + lane];
    sSK[lane + 32] = g_sidK[s*FD + lane + 32];
    __syncwarp();

    unsigned sQb  = su32(sQ);
    unsigned sKb  = su32(sK);
    unsigned sVb  = su32(sV);
    unsigned sSKb = su32(sSK);

    int beg = g_soff[ch][s], end = g_soff[ch][s + 1];

    for (int b0 = beg; b0 < end; b0 += 32) {
        int i = b0 + lane;
        bool act = i < end;
        int ii = act ? i : (end - 1);
        int qid = eqs[ii];
        int rq  = rqs[ii];

        // q = xQ1[qid] + sQ2[s]  (256-bit gathers)
        ull q2[32];
        const char* xqp = (const char*)(g_xQ1 + (size_t)qid * FD);
#pragma unroll
        for (int j = 0; j < 8; j++) {
            ull a, b, c, d;
            ldg4(a, b, c, d, xqp + 32*j);
            ull e, f, g, h;
            lds2(e, f, sQb + 32*j);
            lds2(g, h, sQb + 32*j + 16);
            q2[4*j]   = add2(a, e);
            q2[4*j+1] = add2(b, f);
            q2[4*j+2] = add2(c, g);
            q2[4*j+3] = add2(d, h);
        }

        // scores (unscaled); h >= cnt -> -1e30
        float sc[32];
#pragma unroll
        for (int h = 0; h < 32; h++) {
            if (h < cnt) {
                unsigned kb = sKb + h * (PAD_ROW*4);
                ull acc0 = 0ull, acc1 = 0ull;
#pragma unroll
                for (int j = 0; j < 16; j++) {
                    ull ka, kb2;
                    lds2(ka, kb2, kb + 16*j);
                    acc0 = fma2(q2[2*j],   ka,  acc0);
                    acc1 = fma2(q2[2*j+1], kb2, acc1);
                }
                acc0 = add2(acc0, acc1);
                float lo, hi; upk2(acc0, lo, hi);
                sc[h] = lo + hi;
            } else {
                sc[h] = -1e30f;
            }
        }

        // in-lane masked softmax (scale folded into exp)
        float m = -1e30f;
#pragma unroll
        for (int h = 0; h < 32; h++) m = fmaxf(m, sc[h]);
        float den = 0.f;
#pragma unroll
        for (int h = 0; h < 32; h++) {
            float e = __expf((sc[h] - m) * 0.125f);
            sc[h] = e;
            den += e;
        }
        float inv = 1.f / den;

        // agg = sum_h a_h * V[h][:]
        ull agg2[32];
#pragma unroll
        for (int j = 0; j < 32; j++) agg2[j] = 0ull;
#pragma unroll
        for (int h = 0; h < 32; h++) {
            if (h < cnt) {
                float av = sc[h] * inv;
                ull aa = pk2(av, av);
                unsigned vb = sVb + h * (PAD_ROW*4);
#pragma unroll
                for (int j = 0; j < 16; j++) {
                    ull va, vb2;
                    lds2(va, vb2, vb + 16*j);
                    agg2[2*j]   = fma2(aa, va,  agg2[2*j]);
                    agg2[2*j+1] = fma2(aa, vb2, agg2[2*j+1]);
                }
            }
        }

        // hop-2 logit: p = x[qid].sidK[s] + agg.xMk[qid]  (256-bit gathers)
        ull p0 = 0ull, p1 = 0ull;
        const char* xp = (const char*)(x     + (size_t)qid * FD);
        const char* mp = (const char*)(g_xMk + (size_t)qid * FD);
#pragma unroll
        for (int j = 0; j < 8; j++) {
            ull xa, xb, xc, xd, ma, mb, mc, md, ka, kb2, kc, kd;
            ldg4(xa, xb, xc, xd, xp + 32*j);
            lds2(ka, kb2, sSKb + 32*j);
            lds2(kc, kd,  sSKb + 32*j + 16);
            p0 = fma2(xa, ka,  p0);
            p1 = fma2(xb, kb2, p1);
            p0 = fma2(xc, kc,  p0);
            p1 = fma2(xd, kd,  p1);
            ldg4(ma, mb, mc, md, mp + 32*j);
            p0 = fma2(agg2[4*j],   ma, p0);
            p1 = fma2(agg2[4*j+1], mb, p1);
            p0 = fma2(agg2[4*j+2], mc, p0);
            p1 = fma2(agg2[4*j+3], md, p1);
        }
        p0 = add2(p0, p1);
        float pl, ph; upk2(p0, pl, ph);
        float p = pl + ph;

        if (act) {
            char* op = (char*)(aggc + (size_t)rq * FD);
#pragma unroll
            for (int j = 0; j < 8; j++)
                stg4(op + 32*j, agg2[4*j], agg2[4*j+1], agg2[4*j+2], agg2[4*j+3]);
            sc2c[rq] = 0.125f * p;
        }
    }
}

// ---------------- pass B: segment online softmax + fused finalize ----------------
__global__ void __launch_bounds__(256) k_passB() {
    __shared__ float MVs[FD*FD];
    __shared__ float cVs[FD];
    __shared__ float rb[8][FD];
    int ch = blockIdx.z;
    int t = threadIdx.x;
    for (int i = t; i < FD*FD; i += 256) MVs[i] = g_MV[i];
    if (t < FD) cVs[t] = g_cV[t];
    __syncthreads();
    int lane = t & 31, w = t >> 5;
    int q = blockIdx.x * 8 + w;
    int beg = g_qoff[ch][q], end = g_qoff[ch][q + 1];
    const float* sc2c = g_sc2[ch];
    const int*   sidq = g_sid_by_q[ch];
    const float* aggc = g_agg[ch];

    float m = -3.4e38f, d = 0.f, P0 = 0.f, P1 = 0.f, R0 = 0.f, R1 = 0.f;
    // one-iteration prefetch pipeline
    float sc_n = 0.f, sv0n = 0.f, sv1n = 0.f, ag0n = 0.f, ag1n = 0.f;
    if (beg < end) {
        sc_n = sc2c[beg];
        const float* sv = g_sidV + (size_t)sidq[beg] * FD;
        sv0n = sv[lane]; sv1n = sv[32 + lane];
        const float* ag = aggc + (size_t)beg * FD;
        ag0n = ag[lane]; ag1n = ag[32 + lane];
    }
    for (int i = beg; i < end; i++) {
        float sc = sc_n, sv0 = sv0n, sv1 = sv1n, ag0 = ag0n, ag1 = ag1n;
        if (i + 1 < end) {
            sc_n = sc2c[i + 1];
            const float* sv = g_sidV + (size_t)sidq[i + 1] * FD;
            sv0n = sv[lane]; sv1n = sv[32 + lane];
            const float* ag = aggc + (size_t)(i + 1) * FD;
            ag0n = ag[lane]; ag1n = ag[32 + lane];
        }
        float nm = fmaxf(m, sc);
        float r = __expf(m - nm);
        float e = __expf(sc - nm);
        m = nm;
        d  = d * r + e;
        P0 = fmaf(e, sv0, P0 * r);
        P1 = fmaf(e, sv1, P1 * r);
        R0 = fmaf(e, ag0, R0 * r);
        R1 = fmaf(e, ag1, R1 * r);
    }
    rb[w][lane] = R0; rb[w][32 + lane] = R1;
    __syncwarp();
    float o0 = fmaf(d, cVs[lane],      P0);
    float o1 = fmaf(d, cVs[32 + lane], P1);
#pragma unroll
    for (int k = 0; k < FD; k++) {
        float rk = rb[w][k];
        o0 = fmaf(rk, MVs[k*FD + lane],      o0);
        o1 = fmaf(rk, MVs[k*FD + 32 + lane], o1);
    }
    float inv = 1.f / fmaxf(d, 1e-9f);
    float* o = &g_chO[ch][(size_t)q * FD];
    o[lane]      = o0 * inv;
    o[32 + lane] = o1 * inv;
}

// ---------------- final projection ----------------
__global__ void __launch_bounds__(128) k_project(const float* __restrict__ Wp,
                                                 const float* __restrict__ bp,
                                                 float* __restrict__ out) {
    __shared__ float W1s[FD*FD], W2s[FD*FD];
    int t = threadIdx.x;
    for (int i = t; i < FD*FD; i += 128) { W1s[i] = Wp[i]; W2s[i] = Wp[FD*FD + i]; }
    __syncthreads();
    int q = blockIdx.x * 128 + t;
    float acc[FD];
#pragma unroll
    for (int j = 0; j < FD; j++) acc[j] = bp[j];
    const float* pr = &g_chO[0][(size_t)q * FD];
    const float* nr = &g_chO[1][(size_t)q * FD];
    for (int k = 0; k < FD; k++) {
        float pv = pr[k], nv = nr[k];
#pragma unroll
        for (int j = 0; j < FD; j++)
            acc[j] = fmaf(pv, W1s[k*FD + j], fmaf(nv, W2s[k*FD + j], acc[j]));
    }
    float* o = out + (size_t)q * FD;
#pragma unroll
    for (int j = 0; j < FD; j++) o[j] = acc[j];
}

// ---------------- launch ----------------
extern "C" void kernel_launch(void* const* d_in, const int* in_sizes, int n_in,
                              void* d_out, int out_size) {
    const float* x      = (const float*)d_in[0];
    const float* s_emb  = (const float*)d_in[1];
    const float* W_Q    = (const float*)d_in[2];
    const float* b_Q    = (const float*)d_in[3];
    const float* W_K    = (const float*)d_in[4];
    const float* b_K    = (const float*)d_in[5];
    const float* W_V    = (const float*)d_in[6];
    const float* b_V    = (const float*)d_in[7];
    const float* W_fuse = (const float*)d_in[8];
    const float* b_fuse = (const float*)d_in[9];
    const float* W_K2   = (const float*)d_in[10];
    const float* W_V2   = (const float*)d_in[12];
    const float* b_V2   = (const float*)d_in[13];
    const float* W_proj = (const float*)d_in[14];
    const float* b_proj = (const float*)d_in[15];
    const int* hist_qid_pos = (const int*)d_in[18];
    const int* hist_cnt_pos = (const int*)d_in[19];
    const int* hist_qid_neg = (const int*)d_in[20];
    const int* hist_cnt_neg = (const int*)d_in[21];
    const int* edge_sid_pos = (const int*)d_in[22];
    const int* edge_qid_pos = (const int*)d_in[23];
    const int* edge_sid_neg = (const int*)d_in[24];
    const int* edge_qid_neg = (const int*)d_in[25];
    float* out = (float*)d_out;

    const int passA_smem = 4 * PA_WSM * sizeof(float);  // 71680 B
    cudaFuncSetAttribute(k_passA, cudaFuncAttributeMaxDynamicSharedMemorySize, passA_smem);

    k_small<<<64, 64>>>(W_fuse, W_K2, W_V2, b_fuse, b_V2);

    dim3 prepGrid(QN/128, 4, 7);
    k_prep<<<prepGrid, 128>>>(x, s_emb, W_Q, b_Q, W_K, b_K, W_V, b_V);

    k_zero_counts<<<SN/256, 256>>>();
    k_hist<<<EN/1024, 256>>>(edge_sid_pos, edge_qid_pos, edge_sid_neg, edge_qid_neg);
    k_scan16k<<<4, 1024>>>();
    dim3 scatGrid(EN/256, 1, 2);
    k_scatter<<<scatGrid, 256>>>(edge_sid_pos, edge_qid_pos, edge_sid_neg, edge_qid_neg);

    dim3 aGrid(SN/4, 1, 2);
    k_passA<<<aGrid, 128, passA_smem>>>(x, hist_qid_pos, hist_cnt_pos,
                                        hist_qid_neg, hist_cnt_neg);
    dim3 bGrid(QN/8, 1, 2);
    k_passB<<<bGrid, 256>>>();

    k_project<<<QN/128, 128>>>(W_proj, b_proj, out);
}

// round 5
// speedup vs baseline: 2.2867x; 1.0578x over previous
#include <cuda_runtime.h>
#include <cuda_bf16.h>

#define QN 16384
#define SN 16384
#define FD 64
#define HN 32
#define EN 393216

typedef unsigned long long ull;

// ---------------- packed f32x2 + wide-load helpers ----------------
__device__ __forceinline__ ull pk2(float lo, float hi) {
    ull r; asm("mov.b64 %0,{%1,%2};" : "=l"(r) : "f"(lo), "f"(hi)); return r;
}
__device__ __forceinline__ void upk2(ull v, float& lo, float& hi) {
    asm("mov.b64 {%0,%1},%2;" : "=f"(lo), "=f"(hi) : "l"(v));
}
__device__ __forceinline__ ull fma2(ull a, ull b, ull c) {
    ull r; asm("fma.rn.f32x2 %0,%1,%2,%3;" : "=l"(r) : "l"(a), "l"(b), "l"(c)); return r;
}
__device__ __forceinline__ ull add2(ull a, ull b) {
    ull r; asm("add.rn.f32x2 %0,%1,%2;" : "=l"(r) : "l"(a), "l"(b)); return r;
}
__device__ __forceinline__ void lds2(ull& a, ull& b, unsigned addr) {
    asm volatile("ld.shared.v2.u64 {%0,%1},[%2];" : "=l"(a), "=l"(b) : "r"(addr));
}
// 256-bit global load/store (sm_100+)
__device__ __forceinline__ void ldg4(ull& a, ull& b, ull& c, ull& d, const void* p) {
    asm volatile("ld.global.nc.v4.u64 {%0,%1,%2,%3},[%4];"
                 : "=l"(a), "=l"(b), "=l"(c), "=l"(d) : "l"(p));
}
__device__ __forceinline__ void stg4(void* p, ull a, ull b, ull c, ull d) {
    asm volatile("st.global.v4.u64 [%0],{%1,%2,%3,%4};"
                 :: "l"(p), "l"(a), "l"(b), "l"(c), "l"(d) : "memory");
}
__device__ __forceinline__ unsigned su32(const void* p) {
    unsigned r;
    asm("{ .reg .u64 t; cvta.to.shared.u64 t, %1; cvt.u32.u64 %0, t; }" : "=r"(r) : "l"(p));
    return r;
}

// ---------------- static device scratch (per-channel where needed) ----------------
__device__ __align__(128) float g_xK [QN*FD];
__device__ __align__(128) float g_xV [QN*FD];
__device__ __align__(128) float g_xQ1[QN*FD];
__device__ __align__(128) float g_xMk[QN*FD];
__device__ __align__(128) float g_sQ2 [SN*FD];
__device__ __align__(128) float g_sidK[SN*FD];
__device__ __align__(128) float g_sidV[SN*FD];
__device__ __align__(128) float g_W1K[FD*FD], g_W1V[FD*FD], g_MK[FD*FD], g_MV[FD*FD], g_cV[FD];

__device__ int g_scnt[2][SN], g_qcnt[2][QN], g_scur[2][SN], g_qcur[2][QN];
__device__ int g_soff[2][SN+1], g_qoff[2][QN+1];
__device__ int g_eq_by_s[2][EN];
__device__ int g_rq_by_s[2][EN];
__device__ int g_sid_by_q[2][EN];

__device__ __align__(128) float g_agg[2][(size_t)EN*FD];   // ~201 MB
__device__ float g_sc2[2][EN];
__device__ float g_chO[2][QN*FD];

// ---------------- tiny weight products ----------------
__global__ void k_small(const float* __restrict__ W_fuse, const float* __restrict__ W_K2,
                        const float* __restrict__ W_V2, const float* __restrict__ b_fuse,
                        const float* __restrict__ b_V2) {
    int i = blockIdx.x, j = threadIdx.x;
    float s1k = 0.f, s1v = 0.f, smk = 0.f, smv = 0.f;
    for (int k = 0; k < FD; k++) {
        float wf1 = W_fuse[i*FD + k];
        float wf2 = W_fuse[(FD + i)*FD + k];
        float wk2 = W_K2[k*FD + j];
        float wv2 = W_V2[k*FD + j];
        s1k = fmaf(wf1, wk2, s1k);
        s1v = fmaf(wf1, wv2, s1v);
        smk = fmaf(wf2, wk2, smk);
        smv = fmaf(wf2, wv2, smv);
    }
    g_W1K[i*FD + j] = s1k; g_W1V[i*FD + j] = s1v;
    g_MK [i*FD + j] = smk; g_MV [i*FD + j] = smv;
    if (i == 0) {
        float c = 0.f;
        for (int k = 0; k < FD; k++) c = fmaf(b_fuse[k], W_V2[k*FD + j], c);
        g_cV[j] = c + b_V2[j];
    }
}

// ---------------- fused prep: 7 row-GEMMs in one launch ----------------
__global__ void __launch_bounds__(128) k_prep(const float* __restrict__ x,
                                              const float* __restrict__ s_emb,
                                              const float* __restrict__ W_Q,
                                              const float* __restrict__ b_Q,
                                              const float* __restrict__ W_K,
                                              const float* __restrict__ b_K,
                                              const float* __restrict__ W_V,
                                              const float* __restrict__ b_V) {
    int job = blockIdx.z, cq = blockIdx.y, t = threadIdx.x;
    const float* A; const float* B; const float* bias = b_Q; float* C;
    int transB = 0, addBias = 0;
    switch (job) {
        case 0: A = x;     B = W_K;          bias = b_K; C = g_xK;   addBias = 1; break;
        case 1: A = x;     B = W_V;          bias = b_V; C = g_xV;   addBias = 1; break;
        case 2: A = x;     B = W_Q;                      C = g_xQ1;               break;
        case 3: A = x;     B = g_MK;                     C = g_xMk;  transB = 1;  break;
        case 4: A = s_emb; B = W_Q + FD*FD;  bias = b_Q; C = g_sQ2;  addBias = 1; break;
        case 5: A = s_emb; B = g_W1K;                    C = g_sidK;              break;
        default:A = s_emb; B = g_W1V;                    C = g_sidV;              break;
    }
    __shared__ float Bs[FD*16];
    for (int idx = t; idx < FD*16; idx += 128) {
        int k = idx >> 4, j = idx & 15;
        Bs[idx] = transB ? B[(cq*16 + j)*FD + k] : B[k*FD + cq*16 + j];
    }
    __syncthreads();
    int r = blockIdx.x * 128 + t;
    float acc[16];
#pragma unroll
    for (int j = 0; j < 16; j++) acc[j] = addBias ? bias[cq*16 + j] : 0.f;
    const float4* a4 = (const float4*)(A + (size_t)r * FD);
#pragma unroll
    for (int k4 = 0; k4 < 16; k4++) {
        float4 av = a4[k4];
        const float* bp = Bs + k4*4*16;
#pragma unroll
        for (int j = 0; j < 16; j++) acc[j] = fmaf(av.x, bp[j],      acc[j]);
#pragma unroll
        for (int j = 0; j < 16; j++) acc[j] = fmaf(av.y, bp[16 + j], acc[j]);
#pragma unroll
        for (int j = 0; j < 16; j++) acc[j] = fmaf(av.z, bp[32 + j], acc[j]);
#pragma unroll
        for (int j = 0; j < 16; j++) acc[j] = fmaf(av.w, bp[48 + j], acc[j]);
    }
    float4* c4 = (float4*)(C + (size_t)r * FD + cq*16);
#pragma unroll
    for (int j4 = 0; j4 < 4; j4++)
        c4[j4] = make_float4(acc[4*j4], acc[4*j4+1], acc[4*j4+2], acc[4*j4+3]);
}

// ---------------- counting sort (both channels in each launch) ----------------
__global__ void k_zero_counts() {
    int i = blockIdx.x * blockDim.x + threadIdx.x;
    if (i < SN) {
        g_scnt[0][i] = 0; g_scur[0][i] = 0; g_scnt[1][i] = 0; g_scur[1][i] = 0;
        g_qcnt[0][i] = 0; g_qcur[0][i] = 0; g_qcnt[1][i] = 0; g_qcur[1][i] = 0;
    }
}

__global__ void k_hist(const int* __restrict__ sp, const int* __restrict__ qp,
                       const int* __restrict__ sn, const int* __restrict__ qn) {
    int i = (blockIdx.x * blockDim.x + threadIdx.x) * 4;
    if (i >= EN) return;
    int4 a = *(const int4*)(sp + i);
    int4 b = *(const int4*)(qp + i);
    int4 c = *(const int4*)(sn + i);
    int4 d = *(const int4*)(qn + i);
    atomicAdd(&g_scnt[0][a.x], 1); atomicAdd(&g_scnt[0][a.y], 1);
    atomicAdd(&g_scnt[0][a.z], 1); atomicAdd(&g_scnt[0][a.w], 1);
    atomicAdd(&g_qcnt[0][b.x], 1); atomicAdd(&g_qcnt[0][b.y], 1);
    atomicAdd(&g_qcnt[0][b.z], 1); atomicAdd(&g_qcnt[0][b.w], 1);
    atomicAdd(&g_scnt[1][c.x], 1); atomicAdd(&g_scnt[1][c.y], 1);
    atomicAdd(&g_scnt[1][c.z], 1); atomicAdd(&g_scnt[1][c.w], 1);
    atomicAdd(&g_qcnt[1][d.x], 1); atomicAdd(&g_qcnt[1][d.y], 1);
    atomicAdd(&g_qcnt[1][d.z], 1); atomicAdd(&g_qcnt[1][d.w], 1);
}

// 4 scans (s/q x ch), one block each, all in one launch
__global__ void __launch_bounds__(1024) k_scan16k() {
    int ch = blockIdx.x >> 1, mode = blockIdx.x & 1;
    const int* cnt = mode ? g_qcnt[ch] : g_scnt[ch];
    int* off       = mode ? g_qoff[ch] : g_soff[ch];
    __shared__ int sm[1024];
    int t = threadIdx.x;
    int base = t * 16;
    int loc[16];
    int s = 0;
#pragma unroll
    for (int k = 0; k < 16; k++) { loc[k] = s; s += cnt[base + k]; }
    sm[t] = s;
    __syncthreads();
    for (int o = 1; o < 1024; o <<= 1) {
        int v = (t >= o) ? sm[t - o] : 0;
        __syncthreads();
        sm[t] += v;
        __syncthreads();
    }
    int pre = (t > 0) ? sm[t - 1] : 0;
#pragma unroll
    for (int k = 0; k < 16; k++) off[base + k] = pre + loc[k];
    if (t == 1023) off[16384] = sm[1023];
}

__global__ void k_scatter(const int* __restrict__ sp, const int* __restrict__ qp,
                          const int* __restrict__ sn, const int* __restrict__ qn) {
    int ch = blockIdx.z;
    int i = blockIdx.x * blockDim.x + threadIdx.x;
    if (i >= EN) return;
    const int* es = ch ? sn : sp;
    const int* eq = ch ? qn : qp;
    int s = es[i], q = eq[i];
    int ps = g_soff[ch][s] + atomicAdd(&g_scur[ch][s], 1);
    int pq = g_qoff[ch][q] + atomicAdd(&g_qcur[ch][q], 1);
    g_eq_by_s[ch][ps] = q;
    g_rq_by_s[ch][ps] = pq;
    g_sid_by_q[ch][pq] = s;
}

// ---------------- pass A: lane-owns-edge hop-1 attention, cnt-adaptive ----------------
#define PAD_ROW 68
#define PA_WSM  (2*32*PAD_ROW + 128)   // per-warp smem floats = 4480
__global__ void __launch_bounds__(128, 3) k_passA(const float* __restrict__ x,
                                                  const int* __restrict__ hqp,
                                                  const int* __restrict__ hcp,
                                                  const int* __restrict__ hqn,
                                                  const int* __restrict__ hcn) {
    extern __shared__ float smA[];
    int ch = blockIdx.z;
    const int* hist_qid = ch ? hqn : hqp;
    const int* hist_cnt = ch ? hcn : hcp;
    const int* eqs  = g_eq_by_s[ch];
    const int* rqs  = g_rq_by_s[ch];
    float* aggc = g_agg[ch];
    float* sc2c = g_sc2[ch];

    int lane = threadIdx.x & 31;
    int w    = threadIdx.x >> 5;
    int s    = blockIdx.x * 4 + w;
    float* sK  = smA + w * PA_WSM;
    float* sV  = sK + 32*PAD_ROW;
    float* sQ  = sV + 32*PAD_ROW;     // 64 floats: sQ2 row
    float* sSK = sQ + 64;             // 64 floats: sidK row

    int cnt = hist_cnt[s];
    cnt = min(max(cnt, 0), HN);
    int cpad = (cnt + 7) & ~7;        // active slots padded to chunk of 8

    // load this lane's history row; zero only the partial-chunk tail rows
    if (lane < cnt) {
        int hid = hist_qid[s*HN + lane];
        const float4* kr = (const float4*)(g_xK + (size_t)hid * FD);
        const float4* vr = (const float4*)(g_xV + (size_t)hid * FD);
#pragma unroll
        for (int j = 0; j < 16; j++) {
            *(float4*)(sK + lane*PAD_ROW + 4*j) = kr[j];
            *(float4*)(sV + lane*PAD_ROW + 4*j) = vr[j];
        }
    } else if (lane < cpad) {
        float4 z = make_float4(0.f, 0.f, 0.f, 0.f);
#pragma unroll
        for (int j = 0; j < 16; j++) {
            *(float4*)(sK + lane*PAD_ROW + 4*j) = z;
            *(float4*)(sV + lane*PAD_ROW + 4*j) = z;
        }
    }
    sQ [lane]      = g_sQ2 [s*FD + lane];
    sQ [lane + 32] = g_sQ2 [s*FD + lane + 32];
    sSK[lane]      = g_sidK[s*FD + lane];
    sSK[lane + 32] = g_sidK[s*FD + lane + 32];
    __syncwarp();

    unsigned sQb  = su32(sQ);
    unsigned sKb  = su32(sK);
    unsigned sVb  = su32(sV);
    unsigned sSKb = su32(sSK);

    int beg = g_soff[ch][s], end = g_soff[ch][s + 1];
    if (beg >= end) return;

    // prefetch first sweep indices
    int i0 = beg + lane;
    int ii_n = (i0 < end) ? i0 : (end - 1);
    int qid_n = eqs[ii_n];
    int rq_n  = rqs[ii_n];

    for (int b0 = beg; b0 < end; b0 += 32) {
        int i = b0 + lane;
        bool act = i < end;
        int qid = qid_n, rq = rq_n;
        // prefetch next sweep's indices
        int in = b0 + 32 + lane;
        if (in < end) { qid_n = eqs[in]; rq_n = rqs[in]; }

        // q = xQ1[qid] + sQ2[s]  (256-bit gathers)
        ull q2[32];
        const char* xqp = (const char*)(g_xQ1 + (size_t)qid * FD);
#pragma unroll
        for (int j = 0; j < 8; j++) {
            ull a, b, c, d;
            ldg4(a, b, c, d, xqp + 32*j);
            ull e, f, g, h;
            lds2(e, f, sQb + 32*j);
            lds2(g, h, sQb + 32*j + 16);
            q2[4*j]   = add2(a, e);
            q2[4*j+1] = add2(b, f);
            q2[4*j+2] = add2(c, g);
            q2[4*j+3] = add2(d, h);
        }

        // scores, chunked by 8 (cnt is warp-uniform -> cheap uniform break)
        float sc[32];
        float m = -1e30f;
#pragma unroll
        for (int c8 = 0; c8 < 4; c8++) {
            if (8*c8 >= cnt) break;
#pragma unroll
            for (int hh = 0; hh < 8; hh++) {
                int h = 8*c8 + hh;
                unsigned kb = sKb + h * (PAD_ROW*4);
                ull acc0 = 0ull, acc1 = 0ull;
#pragma unroll
                for (int j = 0; j < 16; j++) {
                    ull ka, kb2;
                    lds2(ka, kb2, kb + 16*j);
                    acc0 = fma2(q2[2*j],   ka,  acc0);
                    acc1 = fma2(q2[2*j+1], kb2, acc1);
                }
                acc0 = add2(acc0, acc1);
                float lo, hi; upk2(acc0, lo, hi);
                float d = (h < cnt) ? (lo + hi) : -1e30f;
                sc[h] = d;
                m = fmaxf(m, d);
            }
        }

        // exp + denominator (chunked)
        float den = 0.f;
#pragma unroll
        for (int c8 = 0; c8 < 4; c8++) {
            if (8*c8 >= cnt) break;
#pragma unroll
            for (int hh = 0; hh < 8; hh++) {
                int h = 8*c8 + hh;
                float e = __expf((sc[h] - m) * 0.125f);
                sc[h] = e;
                den += e;
            }
        }
        float inv = (cnt > 0) ? 1.f / den : 0.f;

        // agg = sum_h a_h * V[h][:] (chunked; rows in partial chunk are zero)
        ull agg2[32];
#pragma unroll
        for (int j = 0; j < 32; j++) agg2[j] = 0ull;
#pragma unroll
        for (int c8 = 0; c8 < 4; c8++) {
            if (8*c8 >= cnt) break;
#pragma unroll
            for (int hh = 0; hh < 8; hh++) {
                int h = 8*c8 + hh;
                float av = sc[h] * inv;
                ull aa = pk2(av, av);
                unsigned vb = sVb + h * (PAD_ROW*4);
#pragma unroll
                for (int j = 0; j < 16; j++) {
                    ull va, vb2;
                    lds2(va, vb2, vb + 16*j);
                    agg2[2*j]   = fma2(aa, va,  agg2[2*j]);
                    agg2[2*j+1] = fma2(aa, vb2, agg2[2*j+1]);
                }
            }
        }

        // hop-2 logit: p = x[qid].sidK[s] + agg.xMk[qid]  (256-bit gathers)
        ull p0 = 0ull, p1 = 0ull;
        const char* xp = (const char*)(x     + (size_t)qid * FD);
        const char* mp = (const char*)(g_xMk + (size_t)qid * FD);
#pragma unroll
        for (int j = 0; j < 8; j++) {
            ull xa, xb, xc, xd, ma, mb, mc, md, ka, kb2, kc, kd;
            ldg4(xa, xb, xc, xd, xp + 32*j);
            lds2(ka, kb2, sSKb + 32*j);
            lds2(kc, kd,  sSKb + 32*j + 16);
            p0 = fma2(xa, ka,  p0);
            p1 = fma2(xb, kb2, p1);
            p0 = fma2(xc, kc,  p0);
            p1 = fma2(xd, kd,  p1);
            ldg4(ma, mb, mc, md, mp + 32*j);
            p0 = fma2(agg2[4*j],   ma, p0);
            p1 = fma2(agg2[4*j+1], mb, p1);
            p0 = fma2(agg2[4*j+2], mc, p0);
            p1 = fma2(agg2[4*j+3], md, p1);
        }
        p0 = add2(p0, p1);
        float pl, ph; upk2(p0, pl, ph);
        float p = pl + ph;

        if (act) {
            char* op = (char*)(aggc + (size_t)rq * FD);
#pragma unroll
            for (int j = 0; j < 8; j++)
                stg4(op + 32*j, agg2[4*j], agg2[4*j+1], agg2[4*j+2], agg2[4*j+3]);
            sc2c[rq] = 0.125f * p;
        }
    }
}

// ---------------- pass B: segment online softmax + fused finalize ----------------
__global__ void __launch_bounds__(256) k_passB() {
    __shared__ float MVs[FD*FD];
    __shared__ float cVs[FD];
    __shared__ float rb[8][FD];
    int ch = blockIdx.z;
    int t = threadIdx.x;
    for (int i = t; i < FD*FD; i += 256) MVs[i] = g_MV[i];
    if (t < FD) cVs[t] = g_cV[t];
    __syncthreads();
    int lane = t & 31, w = t >> 5;
    int q = blockIdx.x * 8 + w;
    int beg = g_qoff[ch][q], end = g_qoff[ch][q + 1];
    const float* sc2c = g_sc2[ch];
    const int*   sidq = g_sid_by_q[ch];
    const float* aggc = g_agg[ch];

    float m = -3.4e38f, d = 0.f, P0 = 0.f, P1 = 0.f, R0 = 0.f, R1 = 0.f;
    float sc_n = 0.f, sv0n = 0.f, sv1n = 0.f, ag0n = 0.f, ag1n = 0.f;
    if (beg < end) {
        sc_n = sc2c[beg];
        const float* sv = g_sidV + (size_t)sidq[beg] * FD;
        sv0n = sv[lane]; sv1n = sv[32 + lane];
        const float* ag = aggc + (size_t)beg * FD;
        ag0n = ag[lane]; ag1n = ag[32 + lane];
    }
    for (int i = beg; i < end; i++) {
        float sc = sc_n, sv0 = sv0n, sv1 = sv1n, ag0 = ag0n, ag1 = ag1n;
        if (i + 1 < end) {
            sc_n = sc2c[i + 1];
            const float* sv = g_sidV + (size_t)sidq[i + 1] * FD;
            sv0n = sv[lane]; sv1n = sv[32 + lane];
            const float* ag = aggc + (size_t)(i + 1) * FD;
            ag0n = ag[lane]; ag1n = ag[32 + lane];
        }
        float nm = fmaxf(m, sc);
        float r = __expf(m - nm);
        float e = __expf(sc - nm);
        m = nm;
        d  = d * r + e;
        P0 = fmaf(e, sv0, P0 * r);
        P1 = fmaf(e, sv1, P1 * r);
        R0 = fmaf(e, ag0, R0 * r);
        R1 = fmaf(e, ag1, R1 * r);
    }
    rb[w][lane] = R0; rb[w][32 + lane] = R1;
    __syncwarp();
    float o0 = fmaf(d, cVs[lane],      P0);
    float o1 = fmaf(d, cVs[32 + lane], P1);
#pragma unroll
    for (int k = 0; k < FD; k++) {
        float rk = rb[w][k];
        o0 = fmaf(rk, MVs[k*FD + lane],      o0);
        o1 = fmaf(rk, MVs[k*FD + 32 + lane], o1);
    }
    float inv = 1.f / fmaxf(d, 1e-9f);
    float* o = &g_chO[ch][(size_t)q * FD];
    o[lane]      = o0 * inv;
    o[32 + lane] = o1 * inv;
}

// ---------------- final projection ----------------
__global__ void __launch_bounds__(128) k_project(const float* __restrict__ Wp,
                                                 const float* __restrict__ bp,
                                                 float* __restrict__ out) {
    __shared__ float W1s[FD*FD], W2s[FD*FD];
    int t = threadIdx.x;
    for (int i = t; i < FD*FD; i += 128) { W1s[i] = Wp[i]; W2s[i] = Wp[FD*FD + i]; }
    __syncthreads();
    int q = blockIdx.x * 128 + t;
    float acc[FD];
#pragma unroll
    for (int j = 0; j < FD; j++) acc[j] = bp[j];
    const float* pr = &g_chO[0][(size_t)q * FD];
    const float* nr = &g_chO[1][(size_t)q * FD];
    for (int k = 0; k < FD; k++) {
        float pv = pr[k], nv = nr[k];
#pragma unroll
        for (int j = 0; j < FD; j++)
            acc[j] = fmaf(pv, W1s[k*FD + j], fmaf(nv, W2s[k*FD + j], acc[j]));
    }
    float* o = out + (size_t)q * FD;
#pragma unroll
    for (int j = 0; j < FD; j++) o[j] = acc[j];
}

// ---------------- launch ----------------
extern "C" void kernel_launch(void* const* d_in, const int* in_sizes, int n_in,
                              void* d_out, int out_size) {
    const float* x      = (const float*)d_in[0];
    const float* s_emb  = (const float*)d_in[1];
    const float* W_Q    = (const float*)d_in[2];
    const float* b_Q    = (const float*)d_in[3];
    const float* W_K    = (const float*)d_in[4];
    const float* b_K    = (const float*)d_in[5];
    const float* W_V    = (const float*)d_in[6];
    const float* b_V    = (const float*)d_in[7];
    const float* W_fuse = (const float*)d_in[8];
    const float* b_fuse = (const float*)d_in[9];
    const float* W_K2   = (const float*)d_in[10];
    const float* W_V2   = (const float*)d_in[12];
    const float* b_V2   = (const float*)d_in[13];
    const float* W_proj = (const float*)d_in[14];
    const float* b_proj = (const float*)d_in[15];
    const int* hist_qid_pos = (const int*)d_in[18];
    const int* hist_cnt_pos = (const int*)d_in[19];
    const int* hist_qid_neg = (const int*)d_in[20];
    const int* hist_cnt_neg = (const int*)d_in[21];
    const int* edge_sid_pos = (const int*)d_in[22];
    const int* edge_qid_pos = (const int*)d_in[23];
    const int* edge_sid_neg = (const int*)d_in[24];
    const int* edge_qid_neg = (const int*)d_in[25];
    float* out = (float*)d_out;

    const int passA_smem = 4 * PA_WSM * sizeof(float);  // 71680 B
    cudaFuncSetAttribute(k_passA, cudaFuncAttributeMaxDynamicSharedMemorySize, passA_smem);

    k_small<<<64, 64>>>(W_fuse, W_K2, W_V2, b_fuse, b_V2);

    dim3 prepGrid(QN/128, 4, 7);
    k_prep<<<prepGrid, 128>>>(x, s_emb, W_Q, b_Q, W_K, b_K, W_V, b_V);

    k_zero_counts<<<SN/256, 256>>>();
    k_hist<<<EN/1024, 256>>>(edge_sid_pos, edge_qid_pos, edge_sid_neg, edge_qid_neg);
    k_scan16k<<<4, 1024>>>();
    dim3 scatGrid(EN/256, 1, 2);
    k_scatter<<<scatGrid, 256>>>(edge_sid_pos, edge_qid_pos, edge_sid_neg, edge_qid_neg);

    dim3 aGrid(SN/4, 1, 2);
    k_passA<<<aGrid, 128, passA_smem>>>(x, hist_qid_pos, hist_cnt_pos,
                                        hist_qid_neg, hist_cnt_neg);
    dim3 bGrid(QN/8, 1, 2);
    k_passB<<<bGrid, 256>>>();

    k_project<<<QN/128, 128>>>(W_proj, b_proj, out);
}